// round 1
// baseline (speedup 1.0000x reference)
#include <cuda_runtime.h>
#include <math.h>

// Problem constants (match reference)
#define T_DIM 1024
#define EPS 1e-7f
#define MARGIN 0.1f
#define MONO_W 0.1f
#define BETA 0.1f

#define BDIM 256            // 256 threads * float4 = 1024 cols = one row
#define ROWS_PER_BLOCK 8

// Global accumulators (device globals: no allocation allowed in kernel_launch)
__device__ double g_bce_sum;
__device__ double g_mono_sum;
__device__ unsigned long long g_mask_cnt;

__global__ void zero_acc_kernel() {
    g_bce_sum = 0.0;
    g_mono_sum = 0.0;
    g_mask_cnt = 0ull;
}

__device__ __forceinline__ float warp_red(float v) {
#pragma unroll
    for (int o = 16; o > 0; o >>= 1) v += __shfl_down_sync(0xFFFFFFFFu, v, o);
    return v;
}
__device__ __forceinline__ int warp_red_i(int v) {
#pragma unroll
    for (int o = 16; o > 0; o >>= 1) v += __shfl_down_sync(0xFFFFFFFFu, v, o);
    return v;
}

__global__ __launch_bounds__(BDIM) void cdf_loss_main(
    const float* __restrict__ F,
    const long long* __restrict__ duration,
    const long long* __restrict__ event_in)
{
    const int tid = threadIdx.x;
    const int row0 = blockIdx.x * ROWS_PER_BLOCK;

    float bce = 0.0f;
    float mono = 0.0f;
    int cnt = 0;

    __shared__ float s_first[BDIM];

    for (int r = 0; r < ROWS_PER_BLOCK; ++r) {
        const int row = row0 + r;
        const float4* rowp = reinterpret_cast<const float4*>(F + (size_t)row * T_DIM);
        float4 v = rowp[tid];

        const int d = (int)duration[row];
        const int e = (int)event_in[row];
        const int c0 = tid * 4;

        // ---- monotonic term ----
        // internal diffs within the float4
        mono += fmaxf(v.x - v.y + MARGIN, 0.0f);
        mono += fmaxf(v.y - v.z + MARGIN, 0.0f);
        mono += fmaxf(v.z - v.w + MARGIN, 0.0f);
        // cross-thread boundary: v.w vs next thread's v.x
        __syncthreads();              // protect previous iteration's reads
        s_first[tid] = v.x;
        __syncthreads();
        if (tid < BDIM - 1)
            mono += fmaxf(v.w - s_first[tid + 1] + MARGIN, 0.0f);

        // ---- BCE term ----
        // event==1: mask all cols, target = (col >= d)
        // event==0: mask cols <= d, target = 0
        float vals[4] = {v.x, v.y, v.z, v.w};
#pragma unroll
        for (int k = 0; k < 4; ++k) {
            const int c = c0 + k;
            const bool m = e ? true : (c <= d);
            if (m) {
                cnt++;
                const float p = fminf(fmaxf(vals[k], EPS), 1.0f - EPS);
                const bool tgt = e && (c >= d);
                // bce_el = -log(p) if target else -log(1-p)
                bce += -__logf(tgt ? p : (1.0f - p));
            }
        }
    }

    // ---- block reduction ----
    bce = warp_red(bce);
    mono = warp_red(mono);
    cnt = warp_red_i(cnt);

    __shared__ float sh_b[BDIM / 32];
    __shared__ float sh_m[BDIM / 32];
    __shared__ int   sh_c[BDIM / 32];
    const int lane = tid & 31, wid = tid >> 5;
    if (lane == 0) { sh_b[wid] = bce; sh_m[wid] = mono; sh_c[wid] = cnt; }
    __syncthreads();
    if (wid == 0) {
        bce  = (lane < BDIM / 32) ? sh_b[lane] : 0.0f;
        mono = (lane < BDIM / 32) ? sh_m[lane] : 0.0f;
        cnt  = (lane < BDIM / 32) ? sh_c[lane] : 0;
        bce = warp_red(bce);
        mono = warp_red(mono);
        cnt = warp_red_i(cnt);
        if (lane == 0) {
            atomicAdd(&g_bce_sum, (double)bce);
            atomicAdd(&g_mono_sum, (double)mono);
            atomicAdd(&g_mask_cnt, (unsigned long long)cnt);
        }
    }
}

__global__ __launch_bounds__(BDIM) void cdf_loss_finalize(
    const float* __restrict__ biases, float* __restrict__ out, int B)
{
    const int tid = threadIdx.x;
    float s = 0.0f;
    for (int i = tid; i < T_DIM; i += BDIM) {
        const float b = biases[i];
        s += b * b;
    }
    s = warp_red(s);
    __shared__ float sh[BDIM / 32];
    const int lane = tid & 31, wid = tid >> 5;
    if (lane == 0) sh[wid] = s;
    __syncthreads();
    if (wid == 0) {
        s = (lane < BDIM / 32) ? sh[lane] : 0.0f;
        s = warp_red(s);
        if (lane == 0) {
            const double bce = g_bce_sum / (double)g_mask_cnt;
            const double mono = g_mono_sum / ((double)B * (double)(T_DIM - 1));
            const double bias2 = (double)s / (double)T_DIM;
            out[0] = (float)(bce + (double)MONO_W * mono + (double)BETA * bias2);
        }
    }
}

extern "C" void kernel_launch(void* const* d_in, const int* in_sizes, int n_in,
                              void* d_out, int out_size) {
    const float*     F       = (const float*)d_in[0];      // [B, T] fp32
    const float*     biases  = (const float*)d_in[1];      // [T] fp32
    const long long* dur     = (const long long*)d_in[2];  // [B] int64
    const long long* ev      = (const long long*)d_in[3];  // [B] int64
    float* out = (float*)d_out;

    const int B = in_sizes[2];
    const int nblocks = B / ROWS_PER_BLOCK;

    zero_acc_kernel<<<1, 1>>>();
    cdf_loss_main<<<nblocks, BDIM>>>(F, dur, ev);
    cdf_loss_finalize<<<1, BDIM>>>(biases, out, B);
}

// round 4
// speedup vs baseline: 1.0525x; 1.0525x over previous
#include <cuda_runtime.h>
#include <math.h>

#define T_DIM 1024
#define EPS 1e-7f
#define MARGIN 0.1f
#define MONO_W 0.1f
#define BETA 0.1f

#define BDIM 256            // 256 threads * float4 = 1024 cols = one row
#define ROWS 8              // rows per block
#define MAXB 32768
#define MAXBLK (MAXB / ROWS)

// Deterministic per-block partials (bce, mono, cnt, pad):
// each block overwrites its own slot every launch -> no init kernel, no atomics.
__device__ float4 g_partials[MAXBLK];

__device__ __forceinline__ float warp_red(float v) {
#pragma unroll
    for (int o = 16; o > 0; o >>= 1) v += __shfl_down_sync(0xFFFFFFFFu, v, o);
    return v;
}
__device__ __forceinline__ double warp_red_d(double v) {
#pragma unroll
    for (int o = 16; o > 0; o >>= 1) v += __shfl_down_sync(0xFFFFFFFFu, v, o);
    return v;
}

__global__ __launch_bounds__(BDIM) void cdf_loss_main(
    const float* __restrict__ F,
    const long long* __restrict__ duration,
    const long long* __restrict__ event_in)
{
    const int tid  = threadIdx.x;
    const int lane = tid & 31;
    const int wid  = tid >> 5;
    const int row0 = blockIdx.x * ROWS;
    const int c0   = tid * 4;

    __shared__ float s_first[ROWS][BDIM];

    // small per-row metadata first (L2-hit broadcasts)
    int d[ROWS], e[ROWS];
#pragma unroll
    for (int r = 0; r < ROWS; ++r) {
        d[r] = (int)duration[row0 + r];
        e[r] = (int)event_in[row0 + r];
    }

    // ---- front-batched independent bulk loads (MLP = ROWS) ----
    float4 v[ROWS];
#pragma unroll
    for (int r = 0; r < ROWS; ++r) {
        const float4* rowp = reinterpret_cast<const float4*>(F + (size_t)(row0 + r) * T_DIM);
        v[r] = rowp[tid];
    }

#pragma unroll
    for (int r = 0; r < ROWS; ++r)
        s_first[r][tid] = v[r].x;
    __syncthreads();   // single barrier: all rows' boundary values published

    float bce = 0.0f;
    float mono = 0.0f;
    int cnt = 0;

#pragma unroll
    for (int r = 0; r < ROWS; ++r) {
        const float4 w = v[r];

        // ---- monotonic term (same mechanism as R1-passing kernel) ----
        mono += fmaxf(w.x - w.y + MARGIN, 0.0f);
        mono += fmaxf(w.y - w.z + MARGIN, 0.0f);
        mono += fmaxf(w.z - w.w + MARGIN, 0.0f);
        if (tid < BDIM - 1)
            mono += fmaxf(w.w - s_first[r][tid + 1] + MARGIN, 0.0f);

        // ---- BCE term (verbatim R1-passing math) ----
        const float vals[4] = {w.x, w.y, w.z, w.w};
        const int dd = d[r], ee = e[r];
#pragma unroll
        for (int k = 0; k < 4; ++k) {
            const int c = c0 + k;
            const bool m = ee ? true : (c <= dd);
            if (m) {
                cnt++;
                const float p = fminf(fmaxf(vals[k], EPS), 1.0f - EPS);
                const bool tgt = ee && (c >= dd);
                bce += -__logf(tgt ? p : (1.0f - p));
            }
        }
    }

    // ---- block reduction ----
    bce  = warp_red(bce);
    mono = warp_red(mono);
    float cf = warp_red((float)cnt);

    __shared__ float sh_b[BDIM / 32];
    __shared__ float sh_m[BDIM / 32];
    __shared__ float sh_c[BDIM / 32];
    if (lane == 0) { sh_b[wid] = bce; sh_m[wid] = mono; sh_c[wid] = cf; }
    __syncthreads();
    if (wid == 0) {
        bce = (lane < BDIM / 32) ? sh_b[lane] : 0.0f;
        mono = (lane < BDIM / 32) ? sh_m[lane] : 0.0f;
        cf  = (lane < BDIM / 32) ? sh_c[lane] : 0.0f;
        bce = warp_red(bce);
        mono = warp_red(mono);
        cf  = warp_red(cf);
        if (lane == 0)
            g_partials[blockIdx.x] = make_float4(bce, mono, cf, 0.0f);
    }
}

__global__ __launch_bounds__(BDIM) void cdf_loss_finalize(
    const float* __restrict__ biases,
    float* __restrict__ out, int B)
{
    const int tid = threadIdx.x;
    const int lane = tid & 31, wid = tid >> 5;
    const int nblk = B / ROWS;

    double sb = 0.0, sm = 0.0, sc = 0.0;
    for (int i = tid; i < nblk; i += BDIM) {
        const float4 p = g_partials[i];
        sb += (double)p.x;
        sm += (double)p.y;
        sc += (double)p.z;
    }

    float s = 0.0f;
    for (int i = tid; i < T_DIM; i += BDIM) {
        const float b = biases[i];
        s += b * b;
    }

    sb = warp_red_d(sb);
    sm = warp_red_d(sm);
    sc = warp_red_d(sc);
    s  = warp_red(s);

    __shared__ double shb[BDIM / 32], shm[BDIM / 32], shc[BDIM / 32];
    __shared__ float  shs[BDIM / 32];
    if (lane == 0) { shb[wid] = sb; shm[wid] = sm; shc[wid] = sc; shs[wid] = s; }
    __syncthreads();
    if (wid == 0) {
        sb = (lane < BDIM / 32) ? shb[lane] : 0.0;
        sm = (lane < BDIM / 32) ? shm[lane] : 0.0;
        sc = (lane < BDIM / 32) ? shc[lane] : 0.0;
        s  = (lane < BDIM / 32) ? shs[lane] : 0.0f;
        sb = warp_red_d(sb);
        sm = warp_red_d(sm);
        sc = warp_red_d(sc);
        s  = warp_red(s);
        if (lane == 0) {
            const double bce   = sb / sc;
            const double mono  = sm / ((double)B * (double)(T_DIM - 1));
            const double bias2 = (double)s / (double)T_DIM;
            out[0] = (float)(bce + (double)MONO_W * mono + (double)BETA * bias2);
        }
    }
}

extern "C" void kernel_launch(void* const* d_in, const int* in_sizes, int n_in,
                              void* d_out, int out_size) {
    const float*     F      = (const float*)d_in[0];      // [B, T] fp32
    const float*     biases = (const float*)d_in[1];      // [T] fp32
    const long long* dur    = (const long long*)d_in[2];  // [B] int64
    const long long* ev     = (const long long*)d_in[3];  // [B] int64
    float* out = (float*)d_out;

    const int B = in_sizes[2];
    const int nblocks = B / ROWS;

    cdf_loss_main<<<nblocks, BDIM>>>(F, dur, ev);
    cdf_loss_finalize<<<1, BDIM>>>(biases, out, B);
}